// round 11
// baseline (speedup 1.0000x reference)
#include <cuda_runtime.h>
#include <math.h>

// ---------------------------------------------------------------------------
// Problem constants (shapes fixed by the dataset)
// ---------------------------------------------------------------------------
#define NMAX 100000
#define EMAX 1200000
#define MAX_SCAN_BLOCKS 128   // ceil(NMAX/1024) = 98 < 128

typedef unsigned long long ULL;

// ---------------------------------------------------------------------------
// Scratch (static __device__ arrays; no allocations allowed)
// All are zero-initialized at module load; g_red*/g_ctr* maintain a
// "zero between launches" invariant (last block of each GEMM resets them).
// ---------------------------------------------------------------------------
__device__ float g_h0[NMAX * 128];   // embedding concat  [N,128]
__device__ float g_agg[NMAX * 128];  // aggregation buffer (layer1 uses 64)
__device__ float g_x1[NMAX * 64];    // layer0 pre-BN
__device__ float g_x2[NMAX * 64];    // layer1 pre-BN
__device__ float g_xf[NMAX * 64];    // fc pre-BN

__device__ int g_deg[NMAX];
__device__ int g_rowstart[NMAX];
__device__ int g_cursor[NMAX];
__device__ int g_csr[EMAX];
__device__ int g_blocksum[MAX_SCAN_BLOCKS];

__device__ float g_red0[128], g_red1[128], g_red2[128];  // [sum(64) | sumsq(64)]
__device__ unsigned int g_ctr0, g_ctr1, g_ctr2;
__device__ float g_bnA0[64], g_bnB0[64];
__device__ float g_bnA1[64], g_bnB1[64];
__device__ float g_bnA2[64], g_bnB2[64];

// ---------------------------------------------------------------------------
// f32x2 helpers (sm_103a packed FFMA2 — only reachable via PTX)
// ---------------------------------------------------------------------------
__device__ __forceinline__ ULL pack2(float lo, float hi) {
    ULL r;
    asm("mov.b64 %0, {%1, %2};" : "=l"(r) : "r"(__float_as_uint(lo)), "r"(__float_as_uint(hi)));
    return r;
}
__device__ __forceinline__ void unpack2(ULL v, float& lo, float& hi) {
    unsigned int a, b;
    asm("mov.b64 {%0, %1}, %2;" : "=r"(a), "=r"(b) : "l"(v));
    lo = __uint_as_float(a);
    hi = __uint_as_float(b);
}
__device__ __forceinline__ ULL ffma2(ULL a, ULL b, ULL c) {
    ULL d;
    asm("fma.rn.f32x2 %0, %1, %2, %3;" : "=l"(d) : "l"(a), "l"(b), "l"(c));
    return d;
}
__device__ __forceinline__ float lrelu(float v) { return v > 0.f ? v : 0.01f * v; }

// ---------------------------------------------------------------------------
// kA: embedding concat (warp per node) + zero g_deg
// ---------------------------------------------------------------------------
__global__ void __launch_bounds__(256) k_init(const int* __restrict__ nd,
                                              const int* __restrict__ nl,
                                              const float* __restrict__ ed,
                                              const float* __restrict__ el, int N) {
    int g = blockIdx.x * 256 + threadIdx.x;
    if (g < N) g_deg[g] = 0;
    int node = g >> 5, lane = g & 31;
    if (node >= N) return;
    float4 v;
    if (lane < 16)
        v = reinterpret_cast<const float4*>(ed + (size_t)nd[node] * 64)[lane];
    else
        v = reinterpret_cast<const float4*>(el + (size_t)nl[node] * 64)[lane - 16];
    reinterpret_cast<float4*>(g_h0 + (size_t)node * 128)[lane] = v;
}

// ---------------------------------------------------------------------------
// CSR build: count -> scan (2 kernels) -> fill
// ---------------------------------------------------------------------------
__global__ void k_count(const int* __restrict__ ei, int E) {
    int e = blockIdx.x * blockDim.x + threadIdx.x;
    if (e < E) atomicAdd(&g_deg[ei[E + e]], 1);
}
__global__ void __launch_bounds__(1024) k_scan1(int N) {
    __shared__ int s[1024];
    int t = threadIdx.x;
    int i = blockIdx.x * 1024 + t;
    int v = (i < N) ? g_deg[i] : 0;
    s[t] = v;
    __syncthreads();
#pragma unroll
    for (int off = 1; off < 1024; off <<= 1) {
        int a = (t >= off) ? s[t - off] : 0;
        __syncthreads();
        s[t] += a;
        __syncthreads();
    }
    if (i < N) g_rowstart[i] = s[t] - v;  // exclusive within block
    if (t == 1023) g_blocksum[blockIdx.x] = s[1023];
}
// scan3': each block reduces g_blocksum[0..blockIdx.x) itself (no scan2 kernel)
__global__ void __launch_bounds__(1024) k_scan3(int N) {
    __shared__ int wsum[32];
    __shared__ int soff;
    int t = threadIdx.x;
    int v = (t < blockIdx.x && t < MAX_SCAN_BLOCKS) ? g_blocksum[t] : 0;
#pragma unroll
    for (int o = 16; o > 0; o >>= 1) v += __shfl_xor_sync(0xffffffffu, v, o);
    if ((t & 31) == 0) wsum[t >> 5] = v;
    __syncthreads();
    if (t == 0) {
        int a = 0;
#pragma unroll
        for (int w = 0; w < 32; w++) a += wsum[w];
        soff = a;
    }
    __syncthreads();
    int i = blockIdx.x * 1024 + t;
    if (i < N) {
        int r = g_rowstart[i] + soff;
        g_rowstart[i] = r;
        g_cursor[i] = r;
    }
}
__global__ void k_fill(const int* __restrict__ ei, int E) {
    int e = blockIdx.x * blockDim.x + threadIdx.x;
    if (e < E) {
        int src = ei[e];
        int dst = ei[E + e];
        int p = atomicAdd(&g_cursor[dst], 1);
        g_csr[p] = src;
    }
}

// ---------------------------------------------------------------------------
// Segment-sum aggregation (warp per node, gather-based, index prefetch).
// BN=true: input is pre-BN x; apply h = lrelu(bnA*x + bnB) per gathered row.
// ---------------------------------------------------------------------------
template <int D, bool BN>
__global__ void __launch_bounds__(256) k_agg(const float* __restrict__ hin,
                                             float* __restrict__ aggout,
                                             const float* __restrict__ bnA,
                                             const float* __restrict__ bnB, int N) {
    int g = blockIdx.x * 256 + threadIdx.x;
    int node = g >> 5, lane = g & 31;
    if (node >= N) return;
    int s = g_rowstart[node];
    int d = g_deg[node];
    if (D == 128) {
        float4 acc = make_float4(0.f, 0.f, 0.f, 0.f);
        int i = 0;
        if (d >= 4) {
            int i0 = g_csr[s], i1 = g_csr[s + 1], i2 = g_csr[s + 2], i3 = g_csr[s + 3];
            for (; i + 8 <= d; i += 4) {
                int j0 = g_csr[s + i + 4], j1 = g_csr[s + i + 5];
                int j2 = g_csr[s + i + 6], j3 = g_csr[s + i + 7];
                float4 r0 = reinterpret_cast<const float4*>(hin + (size_t)i0 * 128)[lane];
                float4 r1 = reinterpret_cast<const float4*>(hin + (size_t)i1 * 128)[lane];
                float4 r2 = reinterpret_cast<const float4*>(hin + (size_t)i2 * 128)[lane];
                float4 r3 = reinterpret_cast<const float4*>(hin + (size_t)i3 * 128)[lane];
                acc.x += r0.x + r1.x + r2.x + r3.x;
                acc.y += r0.y + r1.y + r2.y + r3.y;
                acc.z += r0.z + r1.z + r2.z + r3.z;
                acc.w += r0.w + r1.w + r2.w + r3.w;
                i0 = j0; i1 = j1; i2 = j2; i3 = j3;
            }
            {
                float4 r0 = reinterpret_cast<const float4*>(hin + (size_t)i0 * 128)[lane];
                float4 r1 = reinterpret_cast<const float4*>(hin + (size_t)i1 * 128)[lane];
                float4 r2 = reinterpret_cast<const float4*>(hin + (size_t)i2 * 128)[lane];
                float4 r3 = reinterpret_cast<const float4*>(hin + (size_t)i3 * 128)[lane];
                acc.x += r0.x + r1.x + r2.x + r3.x;
                acc.y += r0.y + r1.y + r2.y + r3.y;
                acc.z += r0.z + r1.z + r2.z + r3.z;
                acc.w += r0.w + r1.w + r2.w + r3.w;
                i += 4;
            }
        }
        for (; i < d; i++) {
            int src = g_csr[s + i];
            float4 r = reinterpret_cast<const float4*>(hin + (size_t)src * 128)[lane];
            acc.x += r.x; acc.y += r.y; acc.z += r.z; acc.w += r.w;
        }
        reinterpret_cast<float4*>(aggout + (size_t)node * 128)[lane] = acc;
    } else {
        float a0 = 0.f, a1 = 0.f, b0 = 0.f, b1 = 0.f;
        if (BN) {
            a0 = bnA[2 * lane]; a1 = bnA[2 * lane + 1];
            b0 = bnB[2 * lane]; b1 = bnB[2 * lane + 1];
        }
        float2 acc = make_float2(0.f, 0.f);
        int i = 0;
        if (d >= 4) {
            int i0 = g_csr[s], i1 = g_csr[s + 1], i2 = g_csr[s + 2], i3 = g_csr[s + 3];
            for (; i + 8 <= d; i += 4) {
                int j0 = g_csr[s + i + 4], j1 = g_csr[s + i + 5];
                int j2 = g_csr[s + i + 6], j3 = g_csr[s + i + 7];
                float2 r0 = reinterpret_cast<const float2*>(hin + (size_t)i0 * 64)[lane];
                float2 r1 = reinterpret_cast<const float2*>(hin + (size_t)i1 * 64)[lane];
                float2 r2 = reinterpret_cast<const float2*>(hin + (size_t)i2 * 64)[lane];
                float2 r3 = reinterpret_cast<const float2*>(hin + (size_t)i3 * 64)[lane];
                if (BN) {
                    acc.x += lrelu(fmaf(r0.x, a0, b0)) + lrelu(fmaf(r1.x, a0, b0)) +
                             lrelu(fmaf(r2.x, a0, b0)) + lrelu(fmaf(r3.x, a0, b0));
                    acc.y += lrelu(fmaf(r0.y, a1, b1)) + lrelu(fmaf(r1.y, a1, b1)) +
                             lrelu(fmaf(r2.y, a1, b1)) + lrelu(fmaf(r3.y, a1, b1));
                } else {
                    acc.x += r0.x + r1.x + r2.x + r3.x;
                    acc.y += r0.y + r1.y + r2.y + r3.y;
                }
                i0 = j0; i1 = j1; i2 = j2; i3 = j3;
            }
            {
                float2 r0 = reinterpret_cast<const float2*>(hin + (size_t)i0 * 64)[lane];
                float2 r1 = reinterpret_cast<const float2*>(hin + (size_t)i1 * 64)[lane];
                float2 r2 = reinterpret_cast<const float2*>(hin + (size_t)i2 * 64)[lane];
                float2 r3 = reinterpret_cast<const float2*>(hin + (size_t)i3 * 64)[lane];
                if (BN) {
                    acc.x += lrelu(fmaf(r0.x, a0, b0)) + lrelu(fmaf(r1.x, a0, b0)) +
                             lrelu(fmaf(r2.x, a0, b0)) + lrelu(fmaf(r3.x, a0, b0));
                    acc.y += lrelu(fmaf(r0.y, a1, b1)) + lrelu(fmaf(r1.y, a1, b1)) +
                             lrelu(fmaf(r2.y, a1, b1)) + lrelu(fmaf(r3.y, a1, b1));
                } else {
                    acc.x += r0.x + r1.x + r2.x + r3.x;
                    acc.y += r0.y + r1.y + r2.y + r3.y;
                }
                i += 4;
            }
        }
        for (; i < d; i++) {
            int src = g_csr[s + i];
            float2 r = reinterpret_cast<const float2*>(hin + (size_t)src * 64)[lane];
            if (BN) {
                acc.x += lrelu(fmaf(r.x, a0, b0));
                acc.y += lrelu(fmaf(r.y, a1, b1));
            } else {
                acc.x += r.x; acc.y += r.y;
            }
        }
        reinterpret_cast<float2*>(aggout + (size_t)node * 64)[lane] = acc;
    }
}

// ---------------------------------------------------------------------------
// Shared epilogue: last block of a GEMM kernel computes BN coefficients,
// then resets the reduction buffer + counter (keeps zero invariant).
// ---------------------------------------------------------------------------
__device__ __forceinline__ void bn_lastblock_epilogue(
    float* sred, float* redp, unsigned int* ctr, int nblocks, int tid,
    const float* gam, const float* bet, float* bnAo, float* bnBo, float invN) {
    if (tid < 128) atomicAdd(&redp[tid], sred[tid]);
    __shared__ unsigned int sIsLast;
    if (tid == 0) {
        __threadfence();
        unsigned int c = atomicAdd(ctr, 1u);
        sIsLast = (c == (unsigned int)(nblocks - 1)) ? 1u : 0u;
    }
    __syncthreads();
    if (sIsLast) {
        if (tid < 64) {
            float s = atomicAdd(&redp[tid], 0.f);       // L2-coherent read
            float q = atomicAdd(&redp[64 + tid], 0.f);
            float mean = s * invN;
            float var = q * invN - mean * mean;
            float a = gam[tid] * rsqrtf(var + 1e-5f);
            bnAo[tid] = a;
            bnBo[tid] = bet[tid] - mean * a;
            redp[tid] = 0.f;
            redp[64 + tid] = 0.f;
        }
        if (tid == 0) *ctr = 0u;
    }
}

// ---------------------------------------------------------------------------
// Fused GIN MLP (channel-pair f32x2).  BNIN: hin is pre-BN, apply bnAi/bnBi.
//   x = (1+eps)*h + agg ; hid = lrelu(x@W1+b1) ; out = hid@W2+b2
// Epilogue: BN partial sums + last-block BN-coefficient computation.
// ---------------------------------------------------------------------------
template <int K, int H, int M, bool BNIN>
__global__ void __launch_bounds__(256) k_mlp2(const float* __restrict__ hin,
                                              const float* __restrict__ agg,
                                              const float* __restrict__ W1,
                                              const float* __restrict__ b1,
                                              const float* __restrict__ W2,
                                              const float* __restrict__ b2,
                                              const float* __restrict__ epsp,
                                              const float* __restrict__ bnAi,
                                              const float* __restrict__ bnBi,
                                              const float* __restrict__ gam,
                                              const float* __restrict__ bet,
                                              float* bnAo, float* bnBo,
                                              float* redp, unsigned int* ctr,
                                              float invN,
                                              float* __restrict__ xout, int N) {
    constexpr int TN = 128, TNp = 132;
    extern __shared__ float sm[];
    float* xs = sm;                 // [K][TNp], reused as hs [H][TNp] (H <= K)
    float* W1s = xs + K * TNp;      // [K][H]
    float* W2s = W1s + K * H;       // [H][M]
    float* sred = W2s + H * M;      // [2*M]

    const int tid = threadIdx.x;
    const int node0 = blockIdx.x * TN;
    const float eps1 = 1.0f + __ldg(epsp);

    for (int i = tid; i < K * H; i += 256) W1s[i] = W1[i];
    for (int i = tid; i < H * M; i += 256) W2s[i] = W2[i];
    if (tid < 2 * M) sred[tid] = 0.f;

    // ---- stage x transposed: xs[k][n] = (1+eps)*h[n][k] + agg[n][k] ----
    {
        int n = tid & 127;
        int half = tid >> 7;
        int node = node0 + n;
        bool ok = node < N;
        const float4* hp = reinterpret_cast<const float4*>(hin + (size_t)node * K);
        const float4* ap = reinterpret_cast<const float4*>(agg + (size_t)node * K);
        int k4b = half * (K / 8);
#pragma unroll
        for (int q = 0; q < K / 8; q++) {
            int k4 = k4b + q;
            float4 hv = ok ? hp[k4] : make_float4(0.f, 0.f, 0.f, 0.f);
            float4 av = ok ? ap[k4] : make_float4(0.f, 0.f, 0.f, 0.f);
            if (BNIN) {
                hv.x = lrelu(fmaf(hv.x, __ldg(bnAi + 4 * k4 + 0), __ldg(bnBi + 4 * k4 + 0)));
                hv.y = lrelu(fmaf(hv.y, __ldg(bnAi + 4 * k4 + 1), __ldg(bnBi + 4 * k4 + 1)));
                hv.z = lrelu(fmaf(hv.z, __ldg(bnAi + 4 * k4 + 2), __ldg(bnBi + 4 * k4 + 2)));
                hv.w = lrelu(fmaf(hv.w, __ldg(bnAi + 4 * k4 + 3), __ldg(bnBi + 4 * k4 + 3)));
            }
            xs[(4 * k4 + 0) * TNp + n] = fmaf(eps1, hv.x, av.x);
            xs[(4 * k4 + 1) * TNp + n] = fmaf(eps1, hv.y, av.y);
            xs[(4 * k4 + 2) * TNp + n] = fmaf(eps1, hv.z, av.z);
            xs[(4 * k4 + 3) * TNp + n] = fmaf(eps1, hv.w, av.w);
        }
    }
    __syncthreads();

    const int w = tid >> 5, l = tid & 31;
    const int nodeblk = w & 3, chblk = w >> 2;
    const int cgrp = l >> 3, ngrp = l & 7;
    const int nb = nodeblk * 32 + ngrp * 4;  // 4 nodes [nb, nb+4)

    // ---- stage 1: x @ W1 + b1 -> lrelu -> hs ----
    constexpr int P1 = H / 16;
    {
        const int cb = chblk * (H / 2) + cgrp * (H / 8);
        ULL acc[4][P1];
#pragma unroll
        for (int j = 0; j < P1; j++) {
            ULL bb = pack2(__ldg(b1 + cb + 2 * j), __ldg(b1 + cb + 2 * j + 1));
#pragma unroll
            for (int p = 0; p < 4; p++) acc[p][j] = bb;
        }
#pragma unroll 2
        for (int k = 0; k < K; k++) {
            float4 av = *reinterpret_cast<const float4*>(xs + k * TNp + nb);
            ULL a0 = pack2(av.x, av.x), a1 = pack2(av.y, av.y);
            ULL a2 = pack2(av.z, av.z), a3 = pack2(av.w, av.w);
            const ULL* wp = reinterpret_cast<const ULL*>(W1s + k * H + cb);
#pragma unroll
            for (int j = 0; j < P1; j++) {
                ULL ww = wp[j];
                acc[0][j] = ffma2(a0, ww, acc[0][j]);
                acc[1][j] = ffma2(a1, ww, acc[1][j]);
                acc[2][j] = ffma2(a2, ww, acc[2][j]);
                acc[3][j] = ffma2(a3, ww, acc[3][j]);
            }
        }
        __syncthreads();  // all xs reads done before overwrite as hs
#pragma unroll
        for (int j = 0; j < P1; j++) {
            float lo[4], hi[4];
#pragma unroll
            for (int p = 0; p < 4; p++) unpack2(acc[p][j], lo[p], hi[p]);
            float4 vlo = make_float4(lrelu(lo[0]), lrelu(lo[1]), lrelu(lo[2]), lrelu(lo[3]));
            float4 vhi = make_float4(lrelu(hi[0]), lrelu(hi[1]), lrelu(hi[2]), lrelu(hi[3]));
            *reinterpret_cast<float4*>(xs + (cb + 2 * j) * TNp + nb) = vlo;
            *reinterpret_cast<float4*>(xs + (cb + 2 * j + 1) * TNp + nb) = vhi;
        }
    }
    __syncthreads();

    // ---- stage 2: hs @ W2 + b2 -> xout (+ BN partial sums) ----
    constexpr int P2 = M / 16;
    {
        const int cb = chblk * (M / 2) + cgrp * (M / 8);
        ULL acc[4][P2];
#pragma unroll
        for (int j = 0; j < P2; j++) {
            ULL bb = pack2(__ldg(b2 + cb + 2 * j), __ldg(b2 + cb + 2 * j + 1));
#pragma unroll
            for (int p = 0; p < 4; p++) acc[p][j] = bb;
        }
#pragma unroll 2
        for (int k = 0; k < H; k++) {
            float4 av = *reinterpret_cast<const float4*>(xs + k * TNp + nb);
            ULL a0 = pack2(av.x, av.x), a1 = pack2(av.y, av.y);
            ULL a2 = pack2(av.z, av.z), a3 = pack2(av.w, av.w);
            const ULL* wp = reinterpret_cast<const ULL*>(W2s + k * M + cb);
#pragma unroll
            for (int j = 0; j < P2; j++) {
                ULL ww = wp[j];
                acc[0][j] = ffma2(a0, ww, acc[0][j]);
                acc[1][j] = ffma2(a1, ww, acc[1][j]);
                acc[2][j] = ffma2(a2, ww, acc[2][j]);
                acc[3][j] = ffma2(a3, ww, acc[3][j]);
            }
        }
        float s[2 * P2], q[2 * P2];
#pragma unroll
        for (int c = 0; c < 2 * P2; c++) { s[c] = 0.f; q[c] = 0.f; }
#pragma unroll
        for (int p = 0; p < 4; p++) {
            int node = node0 + nb + p;
            if (node < N) {
                float v[2 * P2];
#pragma unroll
                for (int j = 0; j < P2; j++) unpack2(acc[p][j], v[2 * j], v[2 * j + 1]);
                *reinterpret_cast<float4*>(xout + (size_t)node * M + cb) =
                    make_float4(v[0], v[1], v[2], v[3]);
                *reinterpret_cast<float4*>(xout + (size_t)node * M + cb + 4) =
                    make_float4(v[4], v[5], v[6], v[7]);
#pragma unroll
                for (int c = 0; c < 2 * P2; c++) { s[c] += v[c]; q[c] += v[c] * v[c]; }
            }
        }
#pragma unroll
        for (int c = 0; c < 2 * P2; c++) {
            atomicAdd(&sred[cb + c], s[c]);
            atomicAdd(&sred[M + cb + c], q[c]);
        }
    }
    __syncthreads();
    bn_lastblock_epilogue(sred, redp, ctr, gridDim.x, tid, gam, bet, bnAo, bnBo, invN);
}

// ---------------------------------------------------------------------------
// FC head GEMM: concat(h0, bn0(x1), bn1(x2)) [256] @ fc_w1 + b -> xf (+BN)
// ---------------------------------------------------------------------------
__global__ void __launch_bounds__(256) k_fc2(const float* __restrict__ h0,
                                             const float* __restrict__ x1,
                                             const float* __restrict__ x2,
                                             const float* __restrict__ bnA0,
                                             const float* __restrict__ bnB0,
                                             const float* __restrict__ bnA1,
                                             const float* __restrict__ bnB1,
                                             const float* __restrict__ W,
                                             const float* __restrict__ b,
                                             const float* __restrict__ gam,
                                             const float* __restrict__ bet,
                                             float* bnAo, float* bnBo,
                                             float* redp, unsigned int* ctr,
                                             float invN,
                                             float* __restrict__ xout, int N) {
    constexpr int K = 256, M = 64, TN = 128, TNp = 132;
    extern __shared__ float sm[];
    float* xs = sm;               // [K][TNp]
    float* Ws = xs + K * TNp;     // [K][M]
    float* sred = Ws + K * M;     // [2*M]

    const int tid = threadIdx.x;
    const int node0 = blockIdx.x * TN;

    for (int i = tid; i < K * M; i += 256) Ws[i] = W[i];
    if (tid < 2 * M) sred[tid] = 0.f;

    // stage concat(h0, h1=bn0(x1), h2=bn1(x2)) transposed
    {
        int n = tid & 127;
        int half = tid >> 7;
        int node = node0 + n;
        bool ok = node < N;
        const float4* p0 = reinterpret_cast<const float4*>(h0 + (size_t)node * 128);
        const float4* p1 = reinterpret_cast<const float4*>(x1 + (size_t)node * 64);
        const float4* p2 = reinterpret_cast<const float4*>(x2 + (size_t)node * 64);
        int k4b = half * 32;
#pragma unroll
        for (int q = 0; q < 32; q++) {
            int k4 = k4b + q;
            float4 v = make_float4(0.f, 0.f, 0.f, 0.f);
            if (ok) {
                if (k4 < 32) {
                    v = p0[k4];
                } else if (k4 < 48) {
                    v = p1[k4 - 32];
                    int c = 4 * (k4 - 32);
                    v.x = lrelu(fmaf(v.x, __ldg(bnA0 + c + 0), __ldg(bnB0 + c + 0)));
                    v.y = lrelu(fmaf(v.y, __ldg(bnA0 + c + 1), __ldg(bnB0 + c + 1)));
                    v.z = lrelu(fmaf(v.z, __ldg(bnA0 + c + 2), __ldg(bnB0 + c + 2)));
                    v.w = lrelu(fmaf(v.w, __ldg(bnA0 + c + 3), __ldg(bnB0 + c + 3)));
                } else {
                    v = p2[k4 - 48];
                    int c = 4 * (k4 - 48);
                    v.x = lrelu(fmaf(v.x, __ldg(bnA1 + c + 0), __ldg(bnB1 + c + 0)));
                    v.y = lrelu(fmaf(v.y, __ldg(bnA1 + c + 1), __ldg(bnB1 + c + 1)));
                    v.z = lrelu(fmaf(v.z, __ldg(bnA1 + c + 2), __ldg(bnB1 + c + 2)));
                    v.w = lrelu(fmaf(v.w, __ldg(bnA1 + c + 3), __ldg(bnB1 + c + 3)));
                }
            }
            xs[(4 * k4 + 0) * TNp + n] = v.x;
            xs[(4 * k4 + 1) * TNp + n] = v.y;
            xs[(4 * k4 + 2) * TNp + n] = v.z;
            xs[(4 * k4 + 3) * TNp + n] = v.w;
        }
    }
    __syncthreads();

    const int w = tid >> 5, l = tid & 31;
    const int nodeblk = w & 3, chblk = w >> 2;
    const int cgrp = l >> 3, ngrp = l & 7;
    const int nb = nodeblk * 32 + ngrp * 4;
    constexpr int P = M / 16;
    const int cb = chblk * (M / 2) + cgrp * (M / 8);

    ULL acc[4][P];
#pragma unroll
    for (int j = 0; j < P; j++) {
        ULL bb = pack2(__ldg(b + cb + 2 * j), __ldg(b + cb + 2 * j + 1));
#pragma unroll
        for (int p = 0; p < 4; p++) acc[p][j] = bb;
    }
#pragma unroll 2
    for (int k = 0; k < K; k++) {
        float4 av = *reinterpret_cast<const float4*>(xs + k * TNp + nb);
        ULL a0 = pack2(av.x, av.x), a1 = pack2(av.y, av.y);
        ULL a2 = pack2(av.z, av.z), a3 = pack2(av.w, av.w);
        const ULL* wp = reinterpret_cast<const ULL*>(Ws + k * M + cb);
#pragma unroll
        for (int j = 0; j < P; j++) {
            ULL ww = wp[j];
            acc[0][j] = ffma2(a0, ww, acc[0][j]);
            acc[1][j] = ffma2(a1, ww, acc[1][j]);
            acc[2][j] = ffma2(a2, ww, acc[2][j]);
            acc[3][j] = ffma2(a3, ww, acc[3][j]);
        }
    }
    float s[2 * P], q[2 * P];
#pragma unroll
    for (int c = 0; c < 2 * P; c++) { s[c] = 0.f; q[c] = 0.f; }
#pragma unroll
    for (int p = 0; p < 4; p++) {
        int node = node0 + nb + p;
        if (node < N) {
            float v[2 * P];
#pragma unroll
            for (int j = 0; j < P; j++) unpack2(acc[p][j], v[2 * j], v[2 * j + 1]);
            *reinterpret_cast<float4*>(xout + (size_t)node * M + cb) =
                make_float4(v[0], v[1], v[2], v[3]);
            *reinterpret_cast<float4*>(xout + (size_t)node * M + cb + 4) =
                make_float4(v[4], v[5], v[6], v[7]);
#pragma unroll
            for (int c = 0; c < 2 * P; c++) { s[c] += v[c]; q[c] += v[c] * v[c]; }
        }
    }
#pragma unroll
    for (int c = 0; c < 2 * P; c++) {
        atomicAdd(&sred[cb + c], s[c]);
        atomicAdd(&sred[M + cb + c], q[c]);
    }
    __syncthreads();
    bn_lastblock_epilogue(sred, redp, ctr, gridDim.x, tid, gam, bet, bnAo, bnBo, invN);
}

// ---------------------------------------------------------------------------
// Final: BN-apply + lrelu + dot(fc_w2) + sigmoid  (warp per node)
// ---------------------------------------------------------------------------
__global__ void __launch_bounds__(256) k_final(const float* __restrict__ xf,
                                               const float* __restrict__ bnA,
                                               const float* __restrict__ bnB,
                                               const float* __restrict__ w2,
                                               const float* __restrict__ b2,
                                               float* __restrict__ out, int N) {
    int g = blockIdx.x * 256 + threadIdx.x;
    int node = g >> 5, lane = g & 31;
    if (node >= N) return;
    int c0 = lane, c1 = lane + 32;
    float v0 = lrelu(fmaf(xf[(size_t)node * 64 + c0], bnA[c0], bnB[c0]));
    float v1 = lrelu(fmaf(xf[(size_t)node * 64 + c1], bnA[c1], bnB[c1]));
    float p = v0 * w2[c0] + v1 * w2[c1];
#pragma unroll
    for (int o = 16; o > 0; o >>= 1) p += __shfl_xor_sync(0xffffffffu, p, o);
    if (lane == 0) out[node] = 1.0f / (1.0f + expf(-(p + b2[0])));
}

// ---------------------------------------------------------------------------
// Launch (11 kernels; launch index 5 = k_agg<128> for ncu visibility)
// ---------------------------------------------------------------------------
extern "C" void kernel_launch(void* const* d_in, const int* in_sizes, int n_in,
                              void* d_out, int out_size) {
    const int* node_deg = (const int*)d_in[0];
    const int* node_lab = (const int*)d_in[1];
    const int* ei       = (const int*)d_in[2];
    const float* emb_deg = (const float*)d_in[3];
    const float* emb_lab = (const float*)d_in[4];
    const float* l0_w1 = (const float*)d_in[5];
    const float* l0_b1 = (const float*)d_in[6];
    const float* l0_w2 = (const float*)d_in[7];
    const float* l0_b2 = (const float*)d_in[8];
    const float* l0_eps = (const float*)d_in[9];
    const float* bn0_g = (const float*)d_in[10];
    const float* bn0_b = (const float*)d_in[11];
    const float* l1_w1 = (const float*)d_in[12];
    const float* l1_b1 = (const float*)d_in[13];
    const float* l1_w2 = (const float*)d_in[14];
    const float* l1_b2 = (const float*)d_in[15];
    const float* l1_eps = (const float*)d_in[16];
    const float* bn1_g = (const float*)d_in[17];
    const float* bn1_b = (const float*)d_in[18];
    const float* fc_w1 = (const float*)d_in[19];
    const float* fc_b1 = (const float*)d_in[20];
    const float* fc_bn_g = (const float*)d_in[21];
    const float* fc_bn_b = (const float*)d_in[22];
    const float* fc_w2 = (const float*)d_in[23];
    const float* fc_b2 = (const float*)d_in[24];
    float* out = (float*)d_out;

    int N = in_sizes[0];
    int E = in_sizes[2] / 2;
    if (N > NMAX) N = NMAX;
    if (E > EMAX) E = EMAX;
    float invN = 1.0f / (float)N;

    float *h0p, *aggp, *x1p, *x2p, *xfp;
    float *bnA0p, *bnB0p, *bnA1p, *bnB1p, *bnA2p, *bnB2p;
    float *red0p, *red1p, *red2p;
    unsigned int *ctr0p, *ctr1p, *ctr2p;
    cudaGetSymbolAddress((void**)&h0p, g_h0);
    cudaGetSymbolAddress((void**)&aggp, g_agg);
    cudaGetSymbolAddress((void**)&x1p, g_x1);
    cudaGetSymbolAddress((void**)&x2p, g_x2);
    cudaGetSymbolAddress((void**)&xfp, g_xf);
    cudaGetSymbolAddress((void**)&bnA0p, g_bnA0);
    cudaGetSymbolAddress((void**)&bnB0p, g_bnB0);
    cudaGetSymbolAddress((void**)&bnA1p, g_bnA1);
    cudaGetSymbolAddress((void**)&bnB1p, g_bnB1);
    cudaGetSymbolAddress((void**)&bnA2p, g_bnA2);
    cudaGetSymbolAddress((void**)&bnB2p, g_bnB2);
    cudaGetSymbolAddress((void**)&red0p, g_red0);
    cudaGetSymbolAddress((void**)&red1p, g_red1);
    cudaGetSymbolAddress((void**)&red2p, g_red2);
    cudaGetSymbolAddress((void**)&ctr0p, g_ctr0);
    cudaGetSymbolAddress((void**)&ctr1p, g_ctr1);
    cudaGetSymbolAddress((void**)&ctr2p, g_ctr2);

    // smem: xs[K][132] + W1[K][H] + W2[H][M] + sred[2M]
    const size_t smem_l0 = (size_t)(128 * 132 + 128 * 128 + 128 * 64 + 128) * 4;  // 166400
    const size_t smem_l1 = (size_t)(64 * 132 + 64 * 64 + 64 * 64 + 128) * 4;      //  67072
    const size_t smem_fc = (size_t)(256 * 132 + 256 * 64 + 128) * 4;              // 201216
    cudaFuncSetAttribute(k_mlp2<128, 128, 64, false>, cudaFuncAttributeMaxDynamicSharedMemorySize, (int)smem_l0);
    cudaFuncSetAttribute(k_mlp2<64, 64, 64, true>, cudaFuncAttributeMaxDynamicSharedMemorySize, (int)smem_l1);
    cudaFuncSetAttribute(k_fc2, cudaFuncAttributeMaxDynamicSharedMemorySize, (int)smem_fc);

    int nbWarpNode = (N * 32 + 255) / 256;
    int nbEdges = (E + 255) / 256;
    int nbScan = (N + 1023) / 1024;
    if (nbScan > MAX_SCAN_BLOCKS) nbScan = MAX_SCAN_BLOCKS;
    int nbMlp = (N + 127) / 128;

    // 0: h0 concat + zero deg
    k_init<<<nbWarpNode, 256>>>(node_deg, node_lab, emb_deg, emb_lab, N);
    // 1-4: CSR build
    k_count<<<nbEdges, 256>>>(ei, E);
    k_scan1<<<nbScan, 1024>>>(N);
    k_scan3<<<nbScan, 1024>>>(N);
    k_fill<<<nbEdges, 256>>>(ei, E);

    // 5: GIN layer 0 aggregation (raw h0)
    k_agg<128, false><<<nbWarpNode, 256>>>(h0p, aggp, nullptr, nullptr, N);
    // 6: layer0 MLP + BN stats + BN coefficients (last block)
    k_mlp2<128, 128, 64, false><<<nbMlp, 256, smem_l0>>>(
        h0p, aggp, l0_w1, l0_b1, l0_w2, l0_b2, l0_eps,
        nullptr, nullptr, bn0_g, bn0_b, bnA0p, bnB0p, red0p, ctr0p, invN, x1p, N);

    // 7: GIN layer 1 aggregation (h1 = lrelu(bn0(x1)) applied inline)
    k_agg<64, true><<<nbWarpNode, 256>>>(x1p, aggp, bnA0p, bnB0p, N);
    // 8: layer1 MLP (hin = x1 with inline BN0) + BN stats/coeffs
    k_mlp2<64, 64, 64, true><<<nbMlp, 256, smem_l1>>>(
        x1p, aggp, l1_w1, l1_b1, l1_w2, l1_b2, l1_eps,
        bnA0p, bnB0p, bn1_g, bn1_b, bnA1p, bnB1p, red1p, ctr1p, invN, x2p, N);

    // 9: FC head (concat h0 | bn0(x1) | bn1(x2)) + BN stats/coeffs
    k_fc2<<<nbMlp, 256, smem_fc>>>(
        h0p, x1p, x2p, bnA0p, bnB0p, bnA1p, bnB1p, fc_w1, fc_b1,
        fc_bn_g, fc_bn_b, bnA2p, bnB2p, red2p, ctr2p, invN, xfp, N);

    // 10: BN-apply + lrelu + dot + sigmoid
    k_final<<<nbWarpNode, 256>>>(xfp, bnA2p, bnB2p, fc_w2, fc_b2, out, N);
}